// round 7
// baseline (speedup 1.0000x reference)
#include <cuda_runtime.h>
#include <cuda_bf16.h>
#include <math.h>

#define H 512
#define W 512
#define B 32
#define CELL 16
#define NC 32            // cells per dim
#define NB 31            // blocks per dim
#define ORI 6
#define BLK_FEAT 24      // 2*2*ORI
#define HWsz (H*W)
#define NSTRIPS (B * NC) // 1024 jobs
#define GRID_A 296       // 2 CTAs/SM exactly; each CTA pipelines 3-4 jobs

// scratch: per-cell histograms, (B, 32, 32, 6)
__device__ float g_cells[B * NC * NC * ORI];

// ---------------------------------------------------------------------------
// Phase 2 worker: gradients + binning + per-thread histograms.
// ---------------------------------------------------------------------------
template <bool BORDER>
__device__ __forceinline__ void phase2(
    const float (*sm)[512], int c, bool cok, int strip,
    float& h0, float& h1, float& h2, float& h3, float& h4, float& h5)
{
    const float C30 = 0.8660254037844386f;  // cos 30

    float w0 = sm[0][c];
    float w1 = sm[1][c];

    #pragma unroll
    for (int i = 0; i < 16; i++) {
        const float w2 = sm[i + 2][c];
        float gr = w2 - w0;
        if (BORDER) {
            const int r = strip * CELL + i;
            if (r == 0 || r == H - 1) gr = 0.0f;
        }
        const float gc = cok ? sm[i + 1][c + 1] - sm[i + 1][c - 1] : 0.0f;
        w0 = w1; w1 = w2;

        const float mag = sqrtf(gr * gr + gc * gc);

        // bin = floor((degrees(atan2(gr,gc)) mod 180)/30): canonicalize to
        // upper half-plane, then binary-search the 30-degree sector.
        float X = gc, Y = gr;
        if (Y < 0.0f || (Y == 0.0f && X < 0.0f)) { X = -X; Y = -Y; }
        const bool hi = (-X >= 0.0f);           // angle >= 90
        const float Xr = hi ?  Y : X;
        const float Yr = hi ? -X : Y;
        int bin = hi ? 3 : 0;
        bin += (C30  * Yr - 0.5f * Xr >= 0.0f); // >= 30 (or >= 120)
        bin += (0.5f * Yr - C30  * Xr >= 0.0f); // >= 60 (or >= 150)

        h0 += (bin == 0) ? mag : 0.0f;
        h1 += (bin == 1) ? mag : 0.0f;
        h2 += (bin == 2) ? mag : 0.0f;
        h3 += (bin == 3) ? mag : 0.0f;
        h4 += (bin == 4) ? mag : 0.0f;
        h5 += (bin == 5) ? mag : 0.0f;
    }
}

// ---------------------------------------------------------------------------
// Kernel A: persistent strip CTAs with register-prefetch software pipeline.
// Per job: 18 rows x 256 float2 slots, thread (half,col2) loads 9 row-pairs.
// Loads for job i+1 are issued BEFORE the compute phase of job i, so their
// DRAM latency overlaps compute; the scoreboard wait lands at the next
// store phase's gray FMAs.
// ---------------------------------------------------------------------------
__global__ __launch_bounds__(512) void hog_cells_kernel(
    const float* __restrict__ x, float* __restrict__ cells)
{
    __shared__ float sm[18][512];
    const int tid = threadIdx.x;
    const int c = tid;              // column for phase 2
    const bool cok = (c > 0) && (c < W - 1);

    const int half = tid >> 8;               // 0 or 1: which row of the pair
    const int col2 = (tid & 255);            // float2 slot in row
    const int colb = col2 << 1;              // float column

    float2 Rr[9], Gg[9], Bb[9];

    // ---- prefetch: issue 27 float2 LDGs for job j into registers ----
    auto prefetch = [&](int j) {
        const int strip = j & (NC - 1);
        const int b     = j >> 5;
        const float* xb = x + (size_t)b * 3 * HWsz;
        const int r0 = strip * CELL - 1;
        if (strip != 0 && strip != NC - 1) {
            #pragma unroll
            for (int it = 0; it < 9; it++) {
                const int i = 2 * it + half;
                const float2* base = (const float2*)(xb + (r0 + i) * W) + col2;
                Rr[it] = __ldg(base);
                Gg[it] = __ldg(base + (HWsz >> 1));
                Bb[it] = __ldg(base + HWsz);
            }
        } else {
            #pragma unroll
            for (int it = 0; it < 9; it++) {
                const int i = 2 * it + half;
                const int r = r0 + i;
                if (r >= 0 && r < H) {
                    const float2* base = (const float2*)(xb + r * W) + col2;
                    Rr[it] = __ldg(base);
                    Gg[it] = __ldg(base + (HWsz >> 1));
                    Bb[it] = __ldg(base + HWsz);
                } else {
                    Rr[it] = Gg[it] = Bb[it] = make_float2(0.f, 0.f);
                }
            }
        }
    };

    int job = blockIdx.x;
    if (job < NSTRIPS) prefetch(job);

    for (; job < NSTRIPS; job += GRID_A) {
        const int strip = job & (NC - 1);
        const int b     = job >> 5;
        const bool border = (strip == 0) | (strip == NC - 1);

        __syncthreads();   // all warps done computing from sm (previous job)

        // store phase: gray conversion consumes the prefetched registers
        #pragma unroll
        for (int it = 0; it < 9; it++) {
            const int i = 2 * it + half;
            float2 g;
            g.x = 0.299f * Rr[it].x + 0.587f * Gg[it].x + 0.114f * Bb[it].x;
            g.y = 0.299f * Rr[it].y + 0.587f * Gg[it].y + 0.114f * Bb[it].y;
            *((float2*)&sm[i][colb]) = g;
        }
        __syncthreads();

        // issue next job's loads NOW; they fly during the compute phase
        const int next = job + GRID_A;
        if (next < NSTRIPS) prefetch(next);

        float h0 = 0.f, h1 = 0.f, h2 = 0.f, h3 = 0.f, h4 = 0.f, h5 = 0.f;
        if (!border) phase2<false>(sm, c, cok, strip, h0, h1, h2, h3, h4, h5);
        else         phase2<true >(sm, c, cok, strip, h0, h1, h2, h3, h4, h5);

        // reduce across the 16 lanes of each column group
        #pragma unroll
        for (int s = 8; s; s >>= 1) {
            h0 += __shfl_xor_sync(0xffffffffu, h0, s);
            h1 += __shfl_xor_sync(0xffffffffu, h1, s);
            h2 += __shfl_xor_sync(0xffffffffu, h2, s);
            h3 += __shfl_xor_sync(0xffffffffu, h3, s);
            h4 += __shfl_xor_sync(0xffffffffu, h4, s);
            h5 += __shfl_xor_sync(0xffffffffu, h5, s);
        }

        if ((c & 15) == 0) {
            const int cellx = c >> 4;
            float* dst = cells + (((size_t)b * NC + strip) * NC + cellx) * ORI;
            const float inv = 1.0f / (CELL * CELL);
            dst[0] = h0 * inv;
            dst[1] = h1 * inv;
            dst[2] = h2 * inv;
            dst[3] = h3 * inv;
            dst[4] = h4 * inv;
            dst[5] = h5 * inv;
        }
    }

#if __CUDA_ARCH__ >= 900
    cudaTriggerProgrammaticLaunchCompletion();
#endif
}

// ---------------------------------------------------------------------------
// Kernel B: 8 lanes per HOG block; rsqrt-based L2-Hys. PDL-launched so its
// ramp overlaps kernel A's tail.
// ---------------------------------------------------------------------------
__global__ __launch_bounds__(256) void hog_blocks_kernel(
    const float* __restrict__ cells, float* __restrict__ out)
{
#if __CUDA_ARCH__ >= 900
    cudaGridDependencySynchronize();
#endif

    const int t = blockIdx.x * blockDim.x + threadIdx.x;
    const int g = t >> 3;           // HOG block index
    const int l = t & 7;            // lane within group
    const int total = B * NB * NB;
    if (g >= total) return;

    const int b  = g / (NB * NB);
    const int ij = g - b * (NB * NB);
    const int i  = ij / NB;
    const int j  = ij - i * NB;

    const int row = i + (l >> 2);
    const int off = (l & 3) * 3;
    const float* p = cells + (((size_t)b * NC + row) * NC + j) * ORI + off;

    float v0 = __ldg(p);
    float v1 = __ldg(p + 1);
    float v2 = __ldg(p + 2);

    const float EPS2 = 1e-10f;  // (1e-5)^2

    float ss = v0 * v0 + v1 * v1 + v2 * v2;
    #pragma unroll
    for (int s = 4; s; s >>= 1) ss += __shfl_xor_sync(0xffffffffu, ss, s);
    const float inv_n1 = rsqrtf(ss + EPS2);
    v0 = fminf(v0 * inv_n1, 0.2f);
    v1 = fminf(v1 * inv_n1, 0.2f);
    v2 = fminf(v2 * inv_n1, 0.2f);

    float ss2 = v0 * v0 + v1 * v1 + v2 * v2;
    #pragma unroll
    for (int s = 4; s; s >>= 1) ss2 += __shfl_xor_sync(0xffffffffu, ss2, s);
    const float inv_n2 = rsqrtf(ss2 + EPS2);

    float* o = out + (size_t)g * BLK_FEAT + l * 3;
    o[0] = v0 * inv_n2;
    o[1] = v1 * inv_n2;
    o[2] = v2 * inv_n2;
}

// ---------------------------------------------------------------------------
extern "C" void kernel_launch(void* const* d_in, const int* in_sizes, int n_in,
                              void* d_out, int out_size)
{
    const float* x = (const float*)d_in[0];
    float* out = (float*)d_out;

    float* cells;
    cudaGetSymbolAddress((void**)&cells, g_cells);

    hog_cells_kernel<<<GRID_A, 512>>>(x, cells);

    const int total = B * NB * NB;                 // 30752
    const int threadsB = total * 8;

    cudaLaunchConfig_t cfg = {};
    cfg.gridDim  = dim3((threadsB + 255) / 256);
    cfg.blockDim = dim3(256);
    cfg.dynamicSmemBytes = 0;
    cfg.stream = 0;
    cudaLaunchAttribute attrs[1];
    attrs[0].id = cudaLaunchAttributeProgrammaticStreamSerialization;
    attrs[0].val.programmaticStreamSerializationAllowed = 1;
    cfg.attrs = attrs;
    cfg.numAttrs = 1;
    cudaLaunchKernelEx(&cfg, hog_blocks_kernel, (const float*)cells, out);
}

// round 8
// speedup vs baseline: 1.1370x; 1.1370x over previous
#include <cuda_runtime.h>
#include <cuda_bf16.h>
#include <math.h>

#define H 512
#define W 512
#define B 32
#define CELL 16
#define NC 32            // cells per dim
#define NB 31            // blocks per dim
#define ORI 6
#define BLK_FEAT 24      // 2*2*ORI
#define HWsz (H*W)
#define NSTRIPS (B * NC) // 1024 jobs
#define GRID_A 592       // 148 SMs * 4 CTAs/SM (512thr, 36KB smem)

// scratch: per-cell histograms, (B, 32, 32, 6)
__device__ float g_cells[B * NC * NC * ORI];

// single-instruction MUFU.SQRT (sqrt.approx.f32: 0 -> 0, ~1ulp on normals)
__device__ __forceinline__ float fast_sqrt(float v) {
    float r;
    asm("sqrt.approx.f32 %0, %1;" : "=f"(r) : "f"(v));
    return r;
}

// ---------------------------------------------------------------------------
// Phase 2 worker: gradients + binning + per-thread histograms.
// BORDER=false (interior strips): no per-pixel row checks at all.
// ---------------------------------------------------------------------------
template <bool BORDER>
__device__ __forceinline__ void phase2(
    const float (*sm)[512], int c, bool cok, int strip,
    float& h0, float& h1, float& h2, float& h3, float& h4, float& h5)
{
    const float C30 = 0.8660254037844386f;  // cos 30

    // rolling register window over own column: gr = sm[i+2][c] - sm[i][c]
    float w0 = sm[0][c];
    float w1 = sm[1][c];

    #pragma unroll
    for (int i = 0; i < 16; i++) {
        const float w2 = sm[i + 2][c];
        float gr = w2 - w0;
        if (BORDER) {
            const int r = strip * CELL + i;
            if (r == 0 || r == H - 1) gr = 0.0f;
        }
        const float gc = cok ? sm[i + 1][c + 1] - sm[i + 1][c - 1] : 0.0f;
        w0 = w1; w1 = w2;

        const float mag = fast_sqrt(gr * gr + gc * gc);

        // bin = floor((degrees(atan2(gr,gc)) mod 180)/30): canonicalize to
        // upper half-plane, then binary-search the 30-degree sector.
        float X = gc, Y = gr;
        if (Y < 0.0f || (Y == 0.0f && X < 0.0f)) { X = -X; Y = -Y; }
        const bool hi = (-X >= 0.0f);           // angle >= 90
        const float Xr = hi ?  Y : X;
        const float Yr = hi ? -X : Y;
        int bin = hi ? 3 : 0;
        bin += (C30  * Yr - 0.5f * Xr >= 0.0f); // >= 30 (or >= 120)
        bin += (0.5f * Yr - C30  * Xr >= 0.0f); // >= 60 (or >= 150)

        h0 += (bin == 0) ? mag : 0.0f;
        h1 += (bin == 1) ? mag : 0.0f;
        h2 += (bin == 2) ? mag : 0.0f;
        h3 += (bin == 3) ? mag : 0.0f;
        h4 += (bin == 4) ? mag : 0.0f;
        h5 += (bin == 5) ? mag : 0.0f;
    }
}

// ---------------------------------------------------------------------------
// Kernel A: persistent strip CTAs, float2-vectorized load phase.
// 18 rows x 256 float2-slots = 4608 slots = exactly 9 iterations of 512
// threads: fully unrolled, unpredicated for interior strips.
// ---------------------------------------------------------------------------
__global__ __launch_bounds__(512) void hog_cells_kernel(
    const float* __restrict__ x, float* __restrict__ cells)
{
    __shared__ float sm[18][512];
    const int tid = threadIdx.x;
    const int c = tid;              // column for phase 2
    const bool cok = (c > 0) && (c < W - 1);

    const int lrow_half = tid >> 8;          // 0 or 1
    const int col2 = (tid & 255);            // float2 slot in row
    const int colb = col2 << 1;              // float column

    for (int job = blockIdx.x; job < NSTRIPS; job += GRID_A) {
        const int strip = job & (NC - 1);   // cell row 0..31
        const int b     = job >> 5;         // image

        const float* xb = x + (size_t)b * 3 * HWsz;
        const int r0 = strip * CELL - 1;
        const bool border = (strip == 0) | (strip == NC - 1);

        __syncthreads();   // protect smem from previous iteration's readers

        if (!border) {
            #pragma unroll
            for (int it = 0; it < 9; it++) {
                const int i = 2 * it + lrow_half;      // local row 0..17
                const float2* base = (const float2*)(xb + (r0 + i) * W) + col2;
                const float2 R  = __ldg(base);
                const float2 G  = __ldg(base + (HWsz >> 1));
                const float2 Bc = __ldg(base + HWsz);
                float2 g;
                g.x = 0.299f * R.x + 0.587f * G.x + 0.114f * Bc.x;
                g.y = 0.299f * R.y + 0.587f * G.y + 0.114f * Bc.y;
                *((float2*)&sm[i][colb]) = g;
            }
        } else {
            #pragma unroll
            for (int it = 0; it < 9; it++) {
                const int i = 2 * it + lrow_half;
                const int r = r0 + i;
                float2 g = make_float2(0.f, 0.f);
                if (r >= 0 && r < H) {
                    const float2* base = (const float2*)(xb + r * W) + col2;
                    const float2 R  = __ldg(base);
                    const float2 G  = __ldg(base + (HWsz >> 1));
                    const float2 Bc = __ldg(base + HWsz);
                    g.x = 0.299f * R.x + 0.587f * G.x + 0.114f * Bc.x;
                    g.y = 0.299f * R.y + 0.587f * G.y + 0.114f * Bc.y;
                }
                *((float2*)&sm[i][colb]) = g;
            }
        }
        __syncthreads();

        float h0 = 0.f, h1 = 0.f, h2 = 0.f, h3 = 0.f, h4 = 0.f, h5 = 0.f;

        if (!border) phase2<false>(sm, c, cok, strip, h0, h1, h2, h3, h4, h5);
        else         phase2<true >(sm, c, cok, strip, h0, h1, h2, h3, h4, h5);

        // reduce across the 16 lanes of each column group
        #pragma unroll
        for (int s = 8; s; s >>= 1) {
            h0 += __shfl_xor_sync(0xffffffffu, h0, s);
            h1 += __shfl_xor_sync(0xffffffffu, h1, s);
            h2 += __shfl_xor_sync(0xffffffffu, h2, s);
            h3 += __shfl_xor_sync(0xffffffffu, h3, s);
            h4 += __shfl_xor_sync(0xffffffffu, h4, s);
            h5 += __shfl_xor_sync(0xffffffffu, h5, s);
        }

        if ((c & 15) == 0) {
            const int cellx = c >> 4;
            float* dst = cells + (((size_t)b * NC + strip) * NC + cellx) * ORI;
            const float inv = 1.0f / (CELL * CELL);
            dst[0] = h0 * inv;
            dst[1] = h1 * inv;
            dst[2] = h2 * inv;
            dst[3] = h3 * inv;
            dst[4] = h4 * inv;
            dst[5] = h5 * inv;
        }
    }

#if __CUDA_ARCH__ >= 900
    cudaTriggerProgrammaticLaunchCompletion();
#endif
}

// ---------------------------------------------------------------------------
// Kernel B: 8 lanes per HOG block; rsqrt-based L2-Hys. PDL-launched so its
// ramp overlaps kernel A's tail.
// ---------------------------------------------------------------------------
__global__ __launch_bounds__(256) void hog_blocks_kernel(
    const float* __restrict__ cells, float* __restrict__ out)
{
#if __CUDA_ARCH__ >= 900
    cudaGridDependencySynchronize();
#endif

    const int t = blockIdx.x * blockDim.x + threadIdx.x;
    const int g = t >> 3;           // HOG block index
    const int l = t & 7;            // lane within group
    const int total = B * NB * NB;
    if (g >= total) return;

    const int b  = g / (NB * NB);
    const int ij = g - b * (NB * NB);
    const int i  = ij / NB;
    const int j  = ij - i * NB;

    // lanes 0-3: cell row i (12 contiguous floats); lanes 4-7: row i+1
    const int row = i + (l >> 2);
    const int off = (l & 3) * 3;
    const float* p = cells + (((size_t)b * NC + row) * NC + j) * ORI + off;

    float v0 = __ldg(p);
    float v1 = __ldg(p + 1);
    float v2 = __ldg(p + 2);

    const float EPS2 = 1e-10f;  // (1e-5)^2

    float ss = v0 * v0 + v1 * v1 + v2 * v2;
    #pragma unroll
    for (int s = 4; s; s >>= 1) ss += __shfl_xor_sync(0xffffffffu, ss, s);
    const float inv_n1 = rsqrtf(ss + EPS2);
    v0 = fminf(v0 * inv_n1, 0.2f);
    v1 = fminf(v1 * inv_n1, 0.2f);
    v2 = fminf(v2 * inv_n1, 0.2f);

    float ss2 = v0 * v0 + v1 * v1 + v2 * v2;
    #pragma unroll
    for (int s = 4; s; s >>= 1) ss2 += __shfl_xor_sync(0xffffffffu, ss2, s);
    const float inv_n2 = rsqrtf(ss2 + EPS2);

    float* o = out + (size_t)g * BLK_FEAT + l * 3;
    o[0] = v0 * inv_n2;
    o[1] = v1 * inv_n2;
    o[2] = v2 * inv_n2;
}

// ---------------------------------------------------------------------------
extern "C" void kernel_launch(void* const* d_in, const int* in_sizes, int n_in,
                              void* d_out, int out_size)
{
    const float* x = (const float*)d_in[0];
    float* out = (float*)d_out;

    float* cells;
    cudaGetSymbolAddress((void**)&cells, g_cells);

    hog_cells_kernel<<<GRID_A, 512>>>(x, cells);

    const int total = B * NB * NB;                 // 30752
    const int threadsB = total * 8;

    cudaLaunchConfig_t cfg = {};
    cfg.gridDim  = dim3((threadsB + 255) / 256);
    cfg.blockDim = dim3(256);
    cfg.dynamicSmemBytes = 0;
    cfg.stream = 0;
    cudaLaunchAttribute attrs[1];
    attrs[0].id = cudaLaunchAttributeProgrammaticStreamSerialization;
    attrs[0].val.programmaticStreamSerializationAllowed = 1;
    cfg.attrs = attrs;
    cfg.numAttrs = 1;
    cudaLaunchKernelEx(&cfg, hog_blocks_kernel, (const float*)cells, out);
}

// round 9
// speedup vs baseline: 1.3224x; 1.1631x over previous
#include <cuda_runtime.h>
#include <cuda_bf16.h>
#include <math.h>

#define H 512
#define W 512
#define B 32
#define CELL 16
#define NC 32            // cells per dim
#define NB 31            // blocks per dim
#define ORI 6
#define BLK_FEAT 24      // 2*2*ORI
#define HWsz (H*W)
#define NSTRIPS (B * NC) // 1024 jobs
#define GRID_A 592       // 148 SMs * 4 CTAs/SM (512thr, 36KB smem)

// scratch: per-cell histograms, (B, 32, 32, 6)
__device__ float g_cells[B * NC * NC * ORI];

// single-instruction MUFU.SQRT (sqrt.approx.f32: 0 -> 0, ~1ulp on normals)
__device__ __forceinline__ float fast_sqrt(float v) {
    float r;
    asm("sqrt.approx.f32 %0, %1;" : "=f"(r) : "f"(v));
    return r;
}

// ---------------------------------------------------------------------------
// Phase 2 worker: gradients + suffix-histogram accumulation.
// S_k = sum of mag where bin >= k; the [bin>=k] predicates ARE the 5 sector
// boundary cross-product tests (identical float expressions to the original
// 5-test binning), so no bin integer is ever materialized.
// ---------------------------------------------------------------------------
template <bool BORDER>
__device__ __forceinline__ void phase2(
    const float (*sm)[512], int c, bool cok, int strip,
    float& S0, float& S1, float& S2, float& S3, float& S4, float& S5)
{
    const float C30 = 0.8660254037844386f;  // cos 30

    // rolling register window over own column: gr = sm[i+2][c] - sm[i][c]
    float w0 = sm[0][c];
    float w1 = sm[1][c];

    #pragma unroll
    for (int i = 0; i < 16; i++) {
        const float w2 = sm[i + 2][c];
        float gr = w2 - w0;
        if (BORDER) {
            const int r = strip * CELL + i;
            if (r == 0 || r == H - 1) gr = 0.0f;
        }
        const float gc = cok ? sm[i + 1][c + 1] - sm[i + 1][c - 1] : 0.0f;
        w0 = w1; w1 = w2;

        const float mag = fast_sqrt(gr * gr + gc * gc);

        // canonicalize to upper half-plane (angle mod 180 invariant)
        float X = gc, Y = gr;
        if (Y < 0.0f || (Y == 0.0f && X < 0.0f)) { X = -X; Y = -Y; }

        // hoisted products shared by the 4 oblique boundary tests
        const float a = C30 * Y;   // cos30 * Y
        const float b = 0.5f * X;
        const float cc = 0.5f * Y;
        const float d = C30 * X;

        S0 += mag;                                   // always
        S1 += ( a - b  >= 0.0f) ? mag : 0.0f;        // angle >= 30
        S2 += ( cc - d >= 0.0f) ? mag : 0.0f;        // angle >= 60
        S3 += (-X      >= 0.0f) ? mag : 0.0f;        // angle >= 90
        S4 += (-cc - d >= 0.0f) ? mag : 0.0f;        // angle >= 120
        S5 += (-a - b  >= 0.0f) ? mag : 0.0f;        // angle >= 150
    }
}

// ---------------------------------------------------------------------------
// Kernel A: persistent strip CTAs, float2-vectorized load phase.
// 18 rows x 256 float2-slots = 4608 = exactly 9 iterations of 512 threads.
// ---------------------------------------------------------------------------
__global__ __launch_bounds__(512) void hog_cells_kernel(
    const float* __restrict__ x, float* __restrict__ cells)
{
    __shared__ float sm[18][512];
    const int tid = threadIdx.x;
    const int c = tid;              // column for phase 2
    const bool cok = (c > 0) && (c < W - 1);

    const int lrow_half = tid >> 8;          // 0 or 1
    const int col2 = (tid & 255);            // float2 slot in row
    const int colb = col2 << 1;              // float column

    for (int job = blockIdx.x; job < NSTRIPS; job += GRID_A) {
        const int strip = job & (NC - 1);   // cell row 0..31
        const int b     = job >> 5;         // image

        const float* xb = x + (size_t)b * 3 * HWsz;
        const int r0 = strip * CELL - 1;
        const bool border = (strip == 0) | (strip == NC - 1);

        __syncthreads();   // protect smem from previous iteration's readers

        if (!border) {
            #pragma unroll
            for (int it = 0; it < 9; it++) {
                const int i = 2 * it + lrow_half;      // local row 0..17
                const float2* base = (const float2*)(xb + (r0 + i) * W) + col2;
                const float2 R  = __ldg(base);
                const float2 G  = __ldg(base + (HWsz >> 1));
                const float2 Bc = __ldg(base + HWsz);
                float2 g;
                g.x = 0.299f * R.x + 0.587f * G.x + 0.114f * Bc.x;
                g.y = 0.299f * R.y + 0.587f * G.y + 0.114f * Bc.y;
                *((float2*)&sm[i][colb]) = g;
            }
        } else {
            #pragma unroll
            for (int it = 0; it < 9; it++) {
                const int i = 2 * it + lrow_half;
                const int r = r0 + i;
                float2 g = make_float2(0.f, 0.f);
                if (r >= 0 && r < H) {
                    const float2* base = (const float2*)(xb + r * W) + col2;
                    const float2 R  = __ldg(base);
                    const float2 G  = __ldg(base + (HWsz >> 1));
                    const float2 Bc = __ldg(base + HWsz);
                    g.x = 0.299f * R.x + 0.587f * G.x + 0.114f * Bc.x;
                    g.y = 0.299f * R.y + 0.587f * G.y + 0.114f * Bc.y;
                }
                *((float2*)&sm[i][colb]) = g;
            }
        }
        __syncthreads();

        float S0 = 0.f, S1 = 0.f, S2 = 0.f, S3 = 0.f, S4 = 0.f, S5 = 0.f;

        if (!border) phase2<false>(sm, c, cok, strip, S0, S1, S2, S3, S4, S5);
        else         phase2<true >(sm, c, cok, strip, S0, S1, S2, S3, S4, S5);

        // reduce suffix sums across the 16 lanes of each column group
        #pragma unroll
        for (int s = 8; s; s >>= 1) {
            S0 += __shfl_xor_sync(0xffffffffu, S0, s);
            S1 += __shfl_xor_sync(0xffffffffu, S1, s);
            S2 += __shfl_xor_sync(0xffffffffu, S2, s);
            S3 += __shfl_xor_sync(0xffffffffu, S3, s);
            S4 += __shfl_xor_sync(0xffffffffu, S4, s);
            S5 += __shfl_xor_sync(0xffffffffu, S5, s);
        }

        if ((c & 15) == 0) {
            const int cellx = c >> 4;
            float* dst = cells + (((size_t)b * NC + strip) * NC + cellx) * ORI;
            const float inv = 1.0f / (CELL * CELL);
            dst[0] = (S0 - S1) * inv;
            dst[1] = (S1 - S2) * inv;
            dst[2] = (S2 - S3) * inv;
            dst[3] = (S3 - S4) * inv;
            dst[4] = (S4 - S5) * inv;
            dst[5] = S5 * inv;
        }
    }

#if __CUDA_ARCH__ >= 900
    cudaTriggerProgrammaticLaunchCompletion();
#endif
}

// ---------------------------------------------------------------------------
// Kernel B: 8 lanes per HOG block; rsqrt-based L2-Hys. PDL-launched so its
// ramp overlaps kernel A's tail.
// ---------------------------------------------------------------------------
__global__ __launch_bounds__(256) void hog_blocks_kernel(
    const float* __restrict__ cells, float* __restrict__ out)
{
#if __CUDA_ARCH__ >= 900
    cudaGridDependencySynchronize();
#endif

    const int t = blockIdx.x * blockDim.x + threadIdx.x;
    const int g = t >> 3;           // HOG block index
    const int l = t & 7;            // lane within group
    const int total = B * NB * NB;
    if (g >= total) return;

    const int b  = g / (NB * NB);
    const int ij = g - b * (NB * NB);
    const int i  = ij / NB;
    const int j  = ij - i * NB;

    // lanes 0-3: cell row i (12 contiguous floats); lanes 4-7: row i+1
    const int row = i + (l >> 2);
    const int off = (l & 3) * 3;
    const float* p = cells + (((size_t)b * NC + row) * NC + j) * ORI + off;

    float v0 = __ldg(p);
    float v1 = __ldg(p + 1);
    float v2 = __ldg(p + 2);

    const float EPS2 = 1e-10f;  // (1e-5)^2

    float ss = v0 * v0 + v1 * v1 + v2 * v2;
    #pragma unroll
    for (int s = 4; s; s >>= 1) ss += __shfl_xor_sync(0xffffffffu, ss, s);
    const float inv_n1 = rsqrtf(ss + EPS2);
    v0 = fminf(v0 * inv_n1, 0.2f);
    v1 = fminf(v1 * inv_n1, 0.2f);
    v2 = fminf(v2 * inv_n1, 0.2f);

    float ss2 = v0 * v0 + v1 * v1 + v2 * v2;
    #pragma unroll
    for (int s = 4; s; s >>= 1) ss2 += __shfl_xor_sync(0xffffffffu, ss2, s);
    const float inv_n2 = rsqrtf(ss2 + EPS2);

    float* o = out + (size_t)g * BLK_FEAT + l * 3;
    o[0] = v0 * inv_n2;
    o[1] = v1 * inv_n2;
    o[2] = v2 * inv_n2;
}

// ---------------------------------------------------------------------------
extern "C" void kernel_launch(void* const* d_in, const int* in_sizes, int n_in,
                              void* d_out, int out_size)
{
    const float* x = (const float*)d_in[0];
    float* out = (float*)d_out;

    float* cells;
    cudaGetSymbolAddress((void**)&cells, g_cells);

    hog_cells_kernel<<<GRID_A, 512>>>(x, cells);

    const int total = B * NB * NB;                 // 30752
    const int threadsB = total * 8;

    cudaLaunchConfig_t cfg = {};
    cfg.gridDim  = dim3((threadsB + 255) / 256);
    cfg.blockDim = dim3(256);
    cfg.dynamicSmemBytes = 0;
    cfg.stream = 0;
    cudaLaunchAttribute attrs[1];
    attrs[0].id = cudaLaunchAttributeProgrammaticStreamSerialization;
    attrs[0].val.programmaticStreamSerializationAllowed = 1;
    cfg.attrs = attrs;
    cfg.numAttrs = 1;
    cudaLaunchKernelEx(&cfg, hog_blocks_kernel, (const float*)cells, out);
}